// round 11
// baseline (speedup 1.0000x reference)
#include <cuda_runtime.h>
#include <cuda_bf16.h>
#include <math.h>
#include <stdint.h>

#define BATCH 64
#define TT 512
#define LL 4
#define II 4
#define NN 520          // TT+LL+II
#define HH 768
#define NH 4
#define DOUT 192
#define H4 (HH/4)
#define KCH 36          // 36 K-chunks of 64 (hi,hi,lo x 12)

// ---------------- scratch (device globals; no allocations allowed) ----------------
__device__ float g_X[2][(size_t)BATCH*NN*HH];   // ping-pong node features (fp32 residual path)
__device__ float g_H[(size_t)BATCH*NN*HH];      // h = X @ W^T
__device__ float g_as[BATCH*NN*NH];             // (h*a_s).sum(-1)
__device__ float g_ad[BATCH*NN*NH];             // (h*a_d).sum(-1)
__device__ int   g_excl[2][BATCH*TT];           // [0]=excluded label idx, [1]=excluded image idx
__device__ __nv_bfloat16 g_Ahi[(size_t)BATCH*NN*HH];  // bf16 hi(X)
__device__ __nv_bfloat16 g_Alo[(size_t)BATCH*NN*HH];  // bf16 lo(X)
__device__ __nv_bfloat16 g_Wh[(size_t)3*HH*HH];       // bf16 hi(W)
__device__ __nv_bfloat16 g_Wl[(size_t)3*HH*HH];       // bf16 lo(W)
__device__ float g_wt[(size_t)BATCH*NN*32];     // heavy softmax weights [b][t][h*8+d]
__device__ float g_dinv[BATCH*32];              // heavy 1/den [b][d*4+h]
__device__ float g_hacc[(size_t)BATCH*8*HH];    // heavy agg partials [b][d][c]

__device__ __forceinline__ float warpSum(float v){
    #pragma unroll
    for (int o=16;o;o>>=1) v += __shfl_xor_sync(0xffffffffu, v, o);
    return v;
}
__device__ __forceinline__ float warpMax(float v){
    #pragma unroll
    for (int o=16;o;o>>=1) v = fmaxf(v, __shfl_xor_sync(0xffffffffu, v, o));
    return v;
}
__device__ __forceinline__ float lrelu(float x){ return x > 0.f ? x : 0.2f*x; }

__device__ __forceinline__ uint32_t smem_u32(const void* p){
    uint32_t a;
    asm("{ .reg .u64 t; cvta.to.shared.u64 t, %1; cvt.u32.u64 %0, t; }" : "=r"(a) : "l"(p));
    return a;
}
__device__ __forceinline__ __nv_bfloat16 bflo(float x, __nv_bfloat16 h){
    return __float2bfloat16(x - __bfloat162float(h));
}

// ---------------- W -> bf16 hi/lo ----------------
__global__ void k_wconv(const float* __restrict__ Ws){
    size_t i = (size_t)blockIdx.x*256 + threadIdx.x;
    if (i >= (size_t)3*HH*HH) return;
    float w = Ws[i];
    __nv_bfloat16 h = __float2bfloat16(w);
    g_Wh[i] = h;
    g_Wl[i] = bflo(w, h);
}

// ---------------- zero alpha + heavy accumulators (per layer) ----------------
#define ASZ (BATCH*NN*NH)
#define HACC (BATCH*8*HH)
__global__ void k_zero(){
    int i = blockIdx.x*256 + threadIdx.x;
    if (i < ASZ) g_as[i] = 0.f;
    else if (i < 2*ASZ) g_ad[i-ASZ] = 0.f;
    else if (i < 2*ASZ + HACC) g_hacc[i-2*ASZ] = 0.f;
}

// ---------------- concat [text;label;image] -> X0 (+ bf16 hi/lo) ----------------
__global__ void k_concat(const float4* __restrict__ text, const float4* __restrict__ lab,
                         const float4* __restrict__ img)
{
    size_t idx = (size_t)blockIdx.x*blockDim.x + threadIdx.x;
    const size_t total = (size_t)BATCH*NN*H4;
    if (idx >= total) return;
    int b = (int)(idx / (NN*H4));
    int r = (int)(idx % (NN*H4));
    int n = r / H4;
    int k = r % H4;
    float4 v;
    if (n < TT)          v = text[(size_t)b*TT*H4 + (size_t)n*H4 + k];
    else if (n < TT+LL)  v = lab [(size_t)b*LL*H4 + (size_t)(n-TT)*H4 + k];
    else                 v = img [(size_t)b*II*H4 + (size_t)(n-TT-LL)*H4 + k];
    ((float4*)g_X[0])[idx] = v;
    __nv_bfloat16 hx=__float2bfloat16(v.x), hy=__float2bfloat16(v.y);
    __nv_bfloat16 hz=__float2bfloat16(v.z), hw=__float2bfloat16(v.w);
    ((__nv_bfloat162*)g_Ahi)[2*idx]   = __halves2bfloat162(hx,hy);
    ((__nv_bfloat162*)g_Ahi)[2*idx+1] = __halves2bfloat162(hz,hw);
    ((__nv_bfloat162*)g_Alo)[2*idx]   = __halves2bfloat162(bflo(v.x,hx), bflo(v.y,hy));
    ((__nv_bfloat162*)g_Alo)[2*idx+1] = __halves2bfloat162(bflo(v.z,hz), bflo(v.w,hw));
}

// ---------------- dynamic edges ----------------
__global__ void k_excl(const float* __restrict__ text, const float* __restrict__ lab,
                       const float* __restrict__ img)
{
    __shared__ float sh[8*HH];
    __shared__ float sinv[8];
    int b = blockIdx.x;
    int tid = threadIdx.x;
    for (int i=tid;i<LL*HH;i+=blockDim.x) sh[i]       = lab[(size_t)b*LL*HH + i];
    for (int i=tid;i<II*HH;i+=blockDim.x) sh[LL*HH+i] = img[(size_t)b*II*HH + i];
    __syncthreads();
    int wid = tid>>5, lane = tid&31;
    if (wid < 8){
        float s=0.f;
        for (int k=lane;k<HH;k+=32){ float v=sh[wid*HH+k]; s+=v*v; }
        s = warpSum(s);
        if (lane==0) sinv[wid] = 1.f / fmaxf(sqrtf(s), 1e-8f);
    }
    __syncthreads();
    for (int t=wid;t<TT;t+=8){
        const float* xr = text + (size_t)b*TT*HH + (size_t)t*HH;
        float d0=0,d1=0,d2=0,d3=0,d4=0,d5=0,d6=0,d7=0;
        for (int k=lane;k<HH;k+=32){
            float x = xr[k];
            d0+=x*sh[0*HH+k]; d1+=x*sh[1*HH+k]; d2+=x*sh[2*HH+k]; d3+=x*sh[3*HH+k];
            d4+=x*sh[4*HH+k]; d5+=x*sh[5*HH+k]; d6+=x*sh[6*HH+k]; d7+=x*sh[7*HH+k];
        }
        d0=warpSum(d0); d1=warpSum(d1); d2=warpSum(d2); d3=warpSum(d3);
        d4=warpSum(d4); d5=warpSum(d5); d6=warpSum(d6); d7=warpSum(d7);
        if (lane==0){
            float c0=d0*sinv[0], c1=d1*sinv[1], c2=d2*sinv[2], c3=d3*sinv[3];
            int el=0; float bm=c0;
            if (c1<bm){bm=c1;el=1;} if (c2<bm){bm=c2;el=2;} if (c3<bm){bm=c3;el=3;}
            g_excl[0][b*TT+t]=el;
            float e0=d4*sinv[4], e1=d5*sinv[5], e2=d6*sinv[6], e3=d7*sinv[7];
            int ei=0; bm=e0;
            if (e1<bm){bm=e1;ei=1;} if (e2<bm){bm=e2;ei=2;} if (e3<bm){bm=e3;ei=3;}
            g_excl[1][b*TT+t]=ei;
        }
    }
}

// ---------------- mma.sync bf16-split GEMM + fused alpha partials ----------------
// CTA tile 128x128, 4 warps (2x2 of 64x64), BK=64, 3-stage cp.async, 1 bar/chunk.
// Grid is (N-tiles, M-tiles): consecutive CTAs share the A tile -> A read once from DRAM.
#define BK 64
#define LDSM 72
#define STG_A (128*LDSM*2)            // 18432
#define STG   (2*STG_A)               // 36864
#define GSMEM (3*STG)                 // 110592 -> 2 CTAs/SM

__device__ __forceinline__ void cp16(uint32_t dst, const void* src){
    asm volatile("cp.async.cg.shared.global [%0], [%1], 16;" :: "r"(dst), "l"(src));
}

__global__ void __launch_bounds__(128,2) k_gemm_mma(int layer,
        const float* __restrict__ aw_s, const float* __restrict__ aw_d)
{
    extern __shared__ __align__(16) char dsm[];
    uint32_t smem = smem_u32(dsm);
    int tid = threadIdx.x, lane = tid&31, wid = tid>>5;
    int warp_m = (wid&1)*64;
    int warp_n = (wid>>1)*64;

    const __nv_bfloat16* Wb  = g_Wh + (size_t)layer*HH*HH;
    const __nv_bfloat16* Wlb = g_Wl + (size_t)layer*HH*HH;
    size_t arow0 = (size_t)blockIdx.y*128;     // M tile (slow axis)
    size_t brow0 = (size_t)blockIdx.x*128;     // N tile (fast axis -> A shared in L2)

    float acc[4][8][4];
    #pragma unroll
    for (int mi=0;mi<4;mi++)
        #pragma unroll
        for (int nj=0;nj<8;nj++)
            #pragma unroll
            for (int r=0;r<4;r++) acc[mi][nj][r]=0.f;

    auto issue = [&](int c, int s){
        const __nv_bfloat16* Asrc = (c<24)? g_Ahi : g_Alo;
        const __nv_bfloat16* Bsrc = (c<12)? Wb : ((c<24)? Wlb : Wb);
        int col = (c%12)*BK;
        uint32_t sa  = smem + s*STG;
        uint32_t sbm = smem + s*STG + STG_A;
        #pragma unroll
        for (int i=0;i<8;i++){
            int idx = tid + i*128;
            int r = idx>>3, q = idx&7;
            cp16(sa + (uint32_t)(r*LDSM + q*8)*2,
                 Asrc + (arow0 + r)*HH + col + q*8);
        }
        #pragma unroll
        for (int i=0;i<8;i++){
            int idx = tid + i*128;
            int r = idx>>3, q = idx&7;
            cp16(sbm + (uint32_t)(r*LDSM + q*8)*2,
                 Bsrc + (brow0 + r)*HH + col + q*8);
        }
        asm volatile("cp.async.commit_group;" ::: "memory");
    };

    issue(0,0);
    issue(1,1);

    for (int c=0;c<KCH;c++){
        int s = c%3;
        if (c+1 < KCH) asm volatile("cp.async.wait_group 1;" ::: "memory");
        else           asm volatile("cp.async.wait_group 0;" ::: "memory");
        __syncthreads();
        if (c+2 < KCH) issue(c+2, (c+2)%3);

        uint32_t saA = smem + s*STG;
        uint32_t saB = smem + s*STG + STG_A;
        #pragma unroll
        for (int ks=0;ks<4;ks++){
            int kb = ks*16;
            uint32_t aF[4][4];
            uint32_t bF[8][2];
            #pragma unroll
            for (int mi=0;mi<4;mi++){
                int row = warp_m + mi*16 + (lane&15);
                int col = kb + ((lane>>4)<<3);
                uint32_t ad = saA + (uint32_t)(row*LDSM + col)*2;
                asm volatile("ldmatrix.sync.aligned.m8n8.x4.shared.b16 {%0,%1,%2,%3}, [%4];"
                    : "=r"(aF[mi][0]), "=r"(aF[mi][1]), "=r"(aF[mi][2]), "=r"(aF[mi][3])
                    : "r"(ad));
            }
            #pragma unroll
            for (int ng=0;ng<4;ng++){
                int n = warp_n + ng*16 + (lane&7) + ((lane>>4)<<3);
                int k = kb + (((lane>>3)&1)<<3);
                uint32_t ad = saB + (uint32_t)(n*LDSM + k)*2;
                uint32_t r0,r1,r2,r3;
                asm volatile("ldmatrix.sync.aligned.m8n8.x4.shared.b16 {%0,%1,%2,%3}, [%4];"
                    : "=r"(r0), "=r"(r1), "=r"(r2), "=r"(r3) : "r"(ad));
                bF[ng*2+0][0]=r0; bF[ng*2+0][1]=r1;
                bF[ng*2+1][0]=r2; bF[ng*2+1][1]=r3;
            }
            #pragma unroll
            for (int mi=0;mi<4;mi++)
                #pragma unroll
                for (int nj=0;nj<8;nj++){
                    asm volatile(
                        "mma.sync.aligned.m16n8k16.row.col.f32.bf16.bf16.f32 "
                        "{%0,%1,%2,%3}, {%4,%5,%6,%7}, {%8,%9}, {%0,%1,%2,%3};"
                        : "+f"(acc[mi][nj][0]), "+f"(acc[mi][nj][1]),
                          "+f"(acc[mi][nj][2]), "+f"(acc[mi][nj][3])
                        : "r"(aF[mi][0]), "r"(aF[mi][1]), "r"(aF[mi][2]), "r"(aF[mi][3]),
                          "r"(bF[nj][0]), "r"(bF[nj][1]));
                }
        }
    }

    // ---- epilogue: write H + fused alpha partials (64-col warp block within one head) ----
    int g = lane>>2, t2 = (lane&3)*2;
    int cb = (int)brow0 + warp_n;
    int head = cb / DOUT;
    float asv[16], adv2[16];
    #pragma unroll
    for (int nj=0;nj<8;nj++){
        int c = cb + nj*8 + t2;
        asv[nj*2]   = aw_s[c];  asv[nj*2+1]  = aw_s[c+1];
        adv2[nj*2]  = aw_d[c];  adv2[nj*2+1] = aw_d[c+1];
    }
    #pragma unroll
    for (int mi=0;mi<4;mi++){
        size_t row = arow0 + warp_m + mi*16 + g;
        float* cr0 = g_H + row*HH + cb;
        float* cr1 = g_H + (row+8)*HH + cb;
        float s0=0.f,d0=0.f,s1=0.f,d1=0.f;
        #pragma unroll
        for (int nj=0;nj<8;nj++){
            int col = nj*8 + t2;
            *(float2*)(cr0 + col) = make_float2(acc[mi][nj][0], acc[mi][nj][1]);
            *(float2*)(cr1 + col) = make_float2(acc[mi][nj][2], acc[mi][nj][3]);
            s0 += acc[mi][nj][0]*asv[nj*2] + acc[mi][nj][1]*asv[nj*2+1];
            d0 += acc[mi][nj][0]*adv2[nj*2] + acc[mi][nj][1]*adv2[nj*2+1];
            s1 += acc[mi][nj][2]*asv[nj*2] + acc[mi][nj][3]*asv[nj*2+1];
            d1 += acc[mi][nj][2]*adv2[nj*2] + acc[mi][nj][3]*adv2[nj*2+1];
        }
        s0 += __shfl_xor_sync(0xffffffffu, s0, 1); s0 += __shfl_xor_sync(0xffffffffu, s0, 2);
        d0 += __shfl_xor_sync(0xffffffffu, d0, 1); d0 += __shfl_xor_sync(0xffffffffu, d0, 2);
        s1 += __shfl_xor_sync(0xffffffffu, s1, 1); s1 += __shfl_xor_sync(0xffffffffu, s1, 2);
        d1 += __shfl_xor_sync(0xffffffffu, d1, 1); d1 += __shfl_xor_sync(0xffffffffu, d1, 2);
        if ((lane&3)==0){
            atomicAdd(&g_as[row*NH + head], s0);
            atomicAdd(&g_ad[row*NH + head], d0);
            atomicAdd(&g_as[(row+8)*NH + head], s1);
            atomicAdd(&g_ad[(row+8)*NH + head], d1);
        }
    }
}

// ---------------- text dsts: one warp per (b,t); heavy rows staged in smem ----------
__global__ void __launch_bounds__(256) k_text(int cur, const float* __restrict__ bias,
        const float* __restrict__ gamma, const float* __restrict__ beta,
        float* __restrict__ outp, int isLast)
{
    __shared__ float s_h[8*HH];    // 8 heavy H rows (24KB)
    __shared__ float s_as[32];     // heavy as values
    int tid = threadIdx.x;
    int lane = tid & 31;
    int b = blockIdx.x >> 6;
    size_t nbase = (size_t)b*NN;

    {
        const float4* hs = (const float4*)(g_H + (nbase + TT)*HH);
        #pragma unroll
        for (int i=0;i<6;i++) ((float4*)s_h)[tid + i*256] = hs[tid + i*256];
        if (tid < 32) s_as[tid] = g_as[(nbase + TT)*NH + tid];
    }
    __syncthreads();

    int gw = blockIdx.x*8 + (tid>>5);
    int t = gw % TT;
    const float* Xcur = g_X[cur];
    float* dst; size_t drow;
    if (isLast){ dst = outp;       drow = ((size_t)b*TT + t)*HH; }
    else       { dst = g_X[cur^1]; drow = (nbase + t)*HH; }

    int el = g_excl[0][b*TT+t], ei = g_excl[1][b*TT+t];
    int srcs[9];
    srcs[0]=t;
    srcs[1]=(t>0)? t-1 : t;
    srcs[2]=(t<TT-1)? t+1 : t;
    srcs[3]=0 + (0>=el);
    srcs[4]=1 + (1>=el);
    srcs[5]=2 + (2>=el);
    srcs[6]=LL + 0 + (0>=ei);
    srcs[7]=LL + 1 + (1>=ei);
    srcs[8]=LL + 2 + (2>=ei);
    bool valid1 = (t>0), valid2 = (t<TT-1);

    float4 adv = ((const float4*)g_ad)[nbase + t];
    float adh[4] = {adv.x, adv.y, adv.z, adv.w};
    float w[9][4];
    float mx[4] = {-1e30f,-1e30f,-1e30f,-1e30f};
    #pragma unroll
    for (int e=0;e<9;e++){
        float4 av;
        if (e < 3) av = ((const float4*)g_as)[nbase + srcs[e]];
        else       av = *(const float4*)&s_as[srcs[e]*4];
        float a[4] = {av.x,av.y,av.z,av.w};
        bool v = (e==1)? valid1 : ((e==2)? valid2 : true);
        #pragma unroll
        for (int h=0;h<4;h++){
            float ev = lrelu(a[h] + adh[h]);
            ev = v ? ev : -1e30f;
            w[e][h]=ev;
            mx[h]=fmaxf(mx[h],ev);
        }
    }
    float den[4]={0,0,0,0};
    #pragma unroll
    for (int e=0;e<9;e++)
        #pragma unroll
        for (int h=0;h<4;h++){ float ex=expf(w[e][h]-mx[h]); w[e][h]=ex; den[h]+=ex; }
    #pragma unroll
    for (int h=0;h<4;h++) den[h] = 1.f/(den[h]+1e-16f);
    #pragma unroll
    for (int e=0;e<9;e++)
        #pragma unroll
        for (int h=0;h<4;h++) w[e][h]*=den[h];

    float acc[24];
    #pragma unroll
    for (int i=0;i<24;i++) acc[i]=0.f;
    const float* Hb = g_H + nbase*HH;
    #pragma unroll
    for (int e=0;e<3;e++){
        const float* hr = Hb + (size_t)srcs[e]*HH + lane;
        #pragma unroll
        for (int i=0;i<24;i++) acc[i] += w[e][i/6]*hr[32*i];
    }
    #pragma unroll
    for (int e=3;e<9;e++){
        const float* hr = s_h + srcs[e]*HH + lane;
        #pragma unroll
        for (int i=0;i<24;i++) acc[i] += w[e][i/6]*hr[32*i];
    }
    const float* xr = Xcur + (nbase + t)*HH + lane;
    float s=0.f;
    #pragma unroll
    for (int i=0;i<24;i++){
        int c = lane + 32*i;
        float v = fmaxf(acc[i] + bias[c], 0.f) + xr[32*i];
        acc[i]=v; s+=v;
    }
    s = warpSum(s);
    float mean = s*(1.f/HH);
    float q=0.f;
    #pragma unroll
    for (int i=0;i<24;i++){ float dd=acc[i]-mean; q+=dd*dd; }
    q = warpSum(q);
    float rstd = rsqrtf(q*(1.f/HH)+1e-5f);
    if (isLast){
        #pragma unroll
        for (int i=0;i<24;i++){
            int c = lane+32*i;
            dst[drow + c] = (acc[i]-mean)*rstd*gamma[c] + beta[c];
        }
    } else {
        #pragma unroll
        for (int i=0;i<24;i++){
            int c = lane+32*i;
            float o = (acc[i]-mean)*rstd*gamma[c] + beta[c];
            dst[drow + c] = o;
            __nv_bfloat16 h = __float2bfloat16(o);
            g_Ahi[drow + c] = h;
            g_Alo[drow + c] = bflo(o, h);
        }
    }
}

// ---------------- heavy dsts, split into 3 kernels ----------------
// k_hw: softmax weights for all 8 heavy dsts -> g_wt, g_dinv. One block per batch.
__global__ void __launch_bounds__(768) k_hw()
{
    __shared__ float s_mx[4];
    __shared__ float s_redm[17*4];
    __shared__ float s_redd[17*4];
    int b = blockIdx.x;
    int tid = threadIdx.x, wid = tid>>5, lane = tid&31;
    size_t nbase = (size_t)b*NN;

    for (int d=0; d<8; d++){
        int dl = d&3;
        const int* excl = g_excl[d>>2] + b*TT;
        float4 adv = ((const float4*)g_ad)[nbase + TT + d];
        float e0=-1e30f, e1=-1e30f, e2=-1e30f, e3=-1e30f;
        if (tid < NN){
            bool v = (tid >= TT) || (excl[tid] != dl);
            float4 av = ((const float4*)g_as)[nbase + tid];
            if (v){
                e0 = lrelu(av.x + adv.x);
                e1 = lrelu(av.y + adv.y);
                e2 = lrelu(av.z + adv.z);
                e3 = lrelu(av.w + adv.w);
            }
        }
        if (wid < 17){
            float m0=warpMax(e0), m1=warpMax(e1), m2=warpMax(e2), m3=warpMax(e3);
            if (lane==0){ s_redm[wid*4+0]=m0; s_redm[wid*4+1]=m1; s_redm[wid*4+2]=m2; s_redm[wid*4+3]=m3; }
        }
        __syncthreads();
        if (tid < 4){
            float m=-1e30f;
            #pragma unroll
            for (int wg=0; wg<17; wg++) m = fmaxf(m, s_redm[wg*4+tid]);
            s_mx[tid] = m;
        }
        __syncthreads();
        float x0=0.f,x1=0.f,x2=0.f,x3=0.f;
        if (tid < NN){
            x0 = expf(e0 - s_mx[0]);
            x1 = expf(e1 - s_mx[1]);
            x2 = expf(e2 - s_mx[2]);
            x3 = expf(e3 - s_mx[3]);
            float* wp = g_wt + (nbase + tid)*32;
            wp[0*8+d] = x0;
            wp[1*8+d] = x1;
            wp[2*8+d] = x2;
            wp[3*8+d] = x3;
        }
        if (wid < 17){
            float d0=warpSum(x0), d1=warpSum(x1), d2=warpSum(x2), d3=warpSum(x3);
            if (lane==0){ s_redd[wid*4+0]=d0; s_redd[wid*4+1]=d1; s_redd[wid*4+2]=d2; s_redd[wid*4+3]=d3; }
        }
        __syncthreads();
        if (tid < 4){
            float sm=0.f;
            #pragma unroll
            for (int wg=0; wg<17; wg++) sm += s_redd[wg*4+tid];
            g_dinv[b*32 + d*4 + tid] = 1.f/(sm + 1e-16f);
        }
        __syncthreads();
    }
}

// k_hagg: grid (BATCH, 8); each block aggregates a 65-row t-chunk for all 768 cols x 8 dsts.
#define TCHK 65
__global__ void __launch_bounds__(256) k_hagg()
{
    int b = blockIdx.x, ch = blockIdx.y;
    int tid = threadIdx.x;
    int t0 = ch*TCHK, t1 = t0 + TCHK;       // 8*65 = 520 exact
    int c0=tid, c1=tid+256, c2=tid+512;
    int h0=c0/DOUT, h1=c1/DOUT, h2=c2/DOUT;
    const float* Hb = g_H + (size_t)b*NN*HH;
    const float* Wt = g_wt + (size_t)b*NN*32;
    float a0[8], a1[8], a2[8];
    #pragma unroll
    for (int d=0;d<8;d++){ a0[d]=0.f; a1[d]=0.f; a2[d]=0.f; }
    for (int t=t0; t<t1; t++){
        const float* hr = Hb + (size_t)t*HH;
        const float* wp = Wt + t*32;
        float v0=hr[c0], v1=hr[c1], v2=hr[c2];
        float4 w00=*(const float4*)&wp[h0*8], w01=*(const float4*)&wp[h0*8+4];
        float4 w10=*(const float4*)&wp[h1*8], w11=*(const float4*)&wp[h1*8+4];
        float4 w20=*(const float4*)&wp[h2*8], w21=*(const float4*)&wp[h2*8+4];
        a0[0]+=w00.x*v0; a0[1]+=w00.y*v0; a0[2]+=w00.z*v0; a0[3]+=w00.w*v0;
        a0[4]+=w01.x*v0; a0[5]+=w01.y*v0; a0[6]+=w01.z*v0; a0[7]+=w01.w*v0;
        a1[0]+=w10.x*v1; a1[1]+=w10.y*v1; a1[2]+=w10.z*v1; a1[3]+=w10.w*v1;
        a1[4]+=w11.x*v1; a1[5]+=w11.y*v1; a1[6]+=w11.z*v1; a1[7]+=w11.w*v1;
        a2[0]+=w20.x*v2; a2[1]+=w20.y*v2; a2[2]+=w20.z*v2; a2[3]+=w20.w*v2;
        a2[4]+=w21.x*v2; a2[5]+=w21.y*v2; a2[6]+=w21.z*v2; a2[7]+=w21.w*v2;
    }
    float* acc = g_hacc + (size_t)b*8*HH;
    #pragma unroll
    for (int d=0;d<8;d++){
        atomicAdd(&acc[d*HH + c0], a0[d]);
        atomicAdd(&acc[d*HH + c1], a1[d]);
        atomicAdd(&acc[d*HH + c2], a2[d]);
    }
}

// k_hfin: grid BATCH*8 = one block per heavy dst; bias/ReLU/residual/LN/writeback.
__global__ void __launch_bounds__(256) k_hfin(int cur, const float* __restrict__ bias,
        const float* __restrict__ gamma, const float* __restrict__ beta)
{
    __shared__ float s_red[8], s_red2[8];
    __shared__ float s_stats[2];
    int bd = blockIdx.x;
    int b = bd>>3, d = bd&7;
    int tid = threadIdx.x, wid = tid>>5, lane = tid&31;
    size_t nbase = (size_t)b*NN;
    size_t row = (nbase + TT + d)*HH;
    const float* acc = g_hacc + (size_t)b*8*HH + d*HH;
    int cs[3] = {tid, tid+256, tid+512};
    float y[3];
    #pragma unroll
    for (int i=0;i<3;i++){
        int c = cs[i]; int h = c/DOUT;
        float dinv = g_dinv[b*32 + d*4 + h];
        y[i] = fmaxf(acc[c]*dinv + bias[c], 0.f) + g_X[cur][row + c];
    }
    float ps = y[0]+y[1]+y[2];
    float pq = y[0]*y[0]+y[1]*y[1]+y[2]*y[2];
    ps = warpSum(ps); pq = warpSum(pq);
    if (lane==0){ s_red[wid]=ps; s_red2[wid]=pq; }
    __syncthreads();
    if (tid==0){
        float S=0.f,Q=0.f;
        #pragma unroll
        for (int wg=0;wg<8;wg++){ S+=s_red[wg]; Q+=s_red2[wg]; }
        float mean = S*(1.f/HH);
        float var  = Q*(1.f/HH) - mean*mean;
        s_stats[0]=mean;
        s_stats[1]=rsqrtf(fmaxf(var,0.f)+1e-5f);
    }
    __syncthreads();
    float mean=s_stats[0], rstd=s_stats[1];
    float* xd = g_X[cur^1];
    #pragma unroll
    for (int i=0;i<3;i++){
        int c = cs[i];
        float o = (y[i]-mean)*rstd*gamma[c] + beta[c];
        xd[row + c] = o;
        __nv_bfloat16 hh = __float2bfloat16(o);
        g_Ahi[row + c] = hh;
        g_Alo[row + c] = bflo(o, hh);
    }
}

// ---------------- launch ----------------
extern "C" void kernel_launch(void* const* d_in, const int* in_sizes, int n_in,
                              void* d_out, int out_size)
{
    const float* text = (const float*)d_in[0];
    const float* lab  = (const float*)d_in[1];
    const float* img  = (const float*)d_in[2];
    const float* Ws   = (const float*)d_in[3];
    const float* aws  = (const float*)d_in[4];
    const float* awd  = (const float*)d_in[5];
    const float* bias = (const float*)d_in[6];
    const float* gam  = (const float*)d_in[7];
    const float* bet  = (const float*)d_in[8];
    float* outp = (float*)d_out;

    cudaFuncSetAttribute(k_gemm_mma, cudaFuncAttributeMaxDynamicSharedMemorySize, GSMEM);

    k_wconv<<<(3*HH*HH + 255)/256, 256>>>(Ws);
    {
        size_t total = (size_t)BATCH*NN*H4;
        int blocks = (int)((total + 255)/256);
        k_concat<<<blocks,256>>>((const float4*)text,(const float4*)lab,(const float4*)img);
    }
    k_excl<<<BATCH,256>>>(text, lab, img);

    int cur = 0;
    for (int l=0;l<3;l++){
        k_zero<<<(2*ASZ + HACC + 255)/256, 256>>>();
        k_gemm_mma<<<dim3(HH/128, (BATCH*NN)/128), 128, GSMEM>>>(l, aws + l*HH, awd + l*HH);
        int last = (l==2);
        k_text<<<(BATCH*TT)/8,256>>>(cur, bias+l*HH, gam+l*HH, bet+l*HH, outp, last);
        if (!last){
            k_hw<<<BATCH, 768>>>();
            k_hagg<<<dim3(BATCH, 8), 256>>>();
            k_hfin<<<BATCH*8, 256>>>(cur, bias+l*HH, gam+l*HH, bet+l*HH);
        }
        cur ^= 1;
    }
}